// round 1
// baseline (speedup 1.0000x reference)
#include <cuda_runtime.h>

// Problem constants (fixed shapes from reference)
#define NB 65536   // batch
#define ND 512     // embed dim
#define NP 1024    // prototypes

// Scratch (device globals: no allocation allowed)
static __device__ float g_cnorm[NP * ND];   // normalized centroids, fp32
static __device__ int   g_hard[NB];         // argmax indices

// ---------------------------------------------------------------------------
// Kernel 1: L2-normalize centroids. One block (128 threads) per centroid row.
// ---------------------------------------------------------------------------
__global__ void normalize_centroids(const float* __restrict__ cent) {
    int row = blockIdx.x;
    int t   = threadIdx.x;  // 0..127, each owns one float4 of the 512-d row
    float4 v = reinterpret_cast<const float4*>(cent + (size_t)row * ND)[t];
    float ss = v.x * v.x + v.y * v.y + v.z * v.z + v.w * v.w;
    #pragma unroll
    for (int o = 16; o > 0; o >>= 1) ss += __shfl_down_sync(0xffffffffu, ss, o);
    __shared__ float sred[4];
    if ((t & 31) == 0) sred[t >> 5] = ss;
    __syncthreads();
    float tot   = sred[0] + sred[1] + sred[2] + sred[3];
    float scale = 1.0f / fmaxf(sqrtf(tot), 1e-12f);
    float4 o4 = make_float4(v.x * scale, v.y * scale, v.z * scale, v.w * scale);
    reinterpret_cast<float4*>(g_cnorm + (size_t)row * ND)[t] = o4;
}

// ---------------------------------------------------------------------------
// Kernel 2: fused GEMM + argmax.
// Block: 256 threads, computes TM=64 query rows against all NP=1024 centroids
// in TN=64 column chunks, K in BK=32 chunks. Maintains running (max, idx)
// per row with first-index tie-break (matches jnp.argmax).
// ---------------------------------------------------------------------------
#define TM 64
#define TN 64
#define BK 32

__global__ __launch_bounds__(256) void argmax_kernel(
    const float* __restrict__ q, float* __restrict__ out_hard) {
    __shared__ float sQ[BK][TM];
    __shared__ float sC[BK][TN];

    int tid = threadIdx.x;
    int ty  = tid >> 4;   // 0..15 -> row group (4 rows each)
    int tx  = tid & 15;   // 0..15 -> col group (4 cols each)
    int m0  = blockIdx.x * TM;

    float bestV[4];
    int   bestI[4];
    #pragma unroll
    for (int i = 0; i < 4; i++) { bestV[i] = -3.0e38f; bestI[i] = 0; }

    for (int n0 = 0; n0 < NP; n0 += TN) {
        float acc[4][4];
        #pragma unroll
        for (int i = 0; i < 4; i++)
            #pragma unroll
            for (int j = 0; j < 4; j++) acc[i][j] = 0.0f;

        for (int k0 = 0; k0 < ND; k0 += BK) {
            // Cooperative tile load: 64 rows x 32 cols each for Q and C,
            // stored transposed [k][row] for the inner product loop.
            #pragma unroll
            for (int l = 0; l < 2; l++) {
                int e   = tid + l * 256;   // float4 index 0..511
                int row = e >> 3;          // 0..63
                int c4  = e & 7;           // 0..7 (float4 within 32-col chunk)
                float4 v = reinterpret_cast<const float4*>(q)
                               [(size_t)(m0 + row) * (ND / 4) + (k0 >> 2) + c4];
                sQ[c4 * 4 + 0][row] = v.x;
                sQ[c4 * 4 + 1][row] = v.y;
                sQ[c4 * 4 + 2][row] = v.z;
                sQ[c4 * 4 + 3][row] = v.w;
                float4 w = reinterpret_cast<const float4*>(g_cnorm)
                               [(size_t)(n0 + row) * (ND / 4) + (k0 >> 2) + c4];
                sC[c4 * 4 + 0][row] = w.x;
                sC[c4 * 4 + 1][row] = w.y;
                sC[c4 * 4 + 2][row] = w.z;
                sC[c4 * 4 + 3][row] = w.w;
            }
            __syncthreads();

            #pragma unroll
            for (int kk = 0; kk < BK; kk++) {
                float rq[4], rc[4];
                #pragma unroll
                for (int i = 0; i < 4; i++) rq[i] = sQ[kk][ty * 4 + i];
                #pragma unroll
                for (int j = 0; j < 4; j++) rc[j] = sC[kk][tx * 4 + j];
                #pragma unroll
                for (int i = 0; i < 4; i++)
                    #pragma unroll
                    for (int j = 0; j < 4; j++)
                        acc[i][j] = fmaf(rq[i], rc[j], acc[i][j]);
            }
            __syncthreads();
        }

        // Update running best per row (ascending column order => strict '>'
        // preserves first-max tie-break)
        #pragma unroll
        for (int i = 0; i < 4; i++) {
            #pragma unroll
            for (int j = 0; j < 4; j++) {
                int   col = n0 + tx * 4 + j;
                float v   = acc[i][j];
                if (v > bestV[i]) { bestV[i] = v; bestI[i] = col; }
            }
        }
    }

    // Reduce across the 16 tx-lanes (contiguous lanes within a warp).
    #pragma unroll
    for (int i = 0; i < 4; i++) {
        float v  = bestV[i];
        int   ix = bestI[i];
        #pragma unroll
        for (int o = 8; o > 0; o >>= 1) {
            float ov = __shfl_down_sync(0xffffffffu, v,  o, 16);
            int   oi = __shfl_down_sync(0xffffffffu, ix, o, 16);
            if (ov > v || (ov == v && oi < ix)) { v = ov; ix = oi; }
        }
        if (tx == 0) {
            int r = m0 + ty * 4 + i;
            g_hard[r]   = ix;
            out_hard[r] = (float)ix;
        }
    }
}

// ---------------------------------------------------------------------------
// Kernel 3: write context gather + one-hot ones. Routing zeros come from a
// cudaMemsetAsync beforehand. One block (128 threads) per query.
// ---------------------------------------------------------------------------
__global__ void scatter_outputs(const float* __restrict__ cent,
                                float* __restrict__ out) {
    int qi = blockIdx.x;
    int t  = threadIdx.x;  // 0..127
    int idx = g_hard[qi];
    float4 v = reinterpret_cast<const float4*>(cent + (size_t)idx * ND)[t];
    reinterpret_cast<float4*>(out + (size_t)qi * ND)[t] = v;
    if (t == 0) {
        out[(size_t)NB * ND + NB + (size_t)qi * NP + idx] = 1.0f;
    }
}

// ---------------------------------------------------------------------------
// Launch: out = [context (B*D) | hard (B) | routing (B*P)] as float32
// ---------------------------------------------------------------------------
extern "C" void kernel_launch(void* const* d_in, const int* in_sizes, int n_in,
                              void* d_out, int out_size) {
    const float* q    = (const float*)d_in[0];  // (B, D) fp32
    const float* cent = (const float*)d_in[1];  // (P, D) fp32
    float* out = (float*)d_out;

    normalize_centroids<<<NP, 128>>>(cent);
    argmax_kernel<<<NB / TM, 256>>>(q, out + (size_t)NB * ND);
    cudaMemsetAsync(out + (size_t)NB * ND + NB, 0,
                    (size_t)NB * NP * sizeof(float));
    scatter_outputs<<<NB, 128>>>(cent, out);
}

// round 2
// speedup vs baseline: 5.5375x; 5.5375x over previous
#include <cuda_runtime.h>
#include <cuda_bf16.h>

#define NB 65536   // batch
#define ND 512     // embed dim
#define NP 1024    // prototypes
#define MARGIN 0.08f

// Device-global scratch (no runtime allocation allowed)
static __device__ float          g_cnorm[NP * ND];      // normalized centroids fp32
static __device__ __nv_bfloat16  g_cnorm_bf[NP * ND];   // normalized centroids bf16
static __device__ float          g_logits[(size_t)NB * NP];  // 256 MB approx logits

// ---------------------------------------------------------------------------
// Kernel 1: L2-normalize centroids -> fp32 + bf16 copies.
// ---------------------------------------------------------------------------
__global__ void normalize_centroids(const float* __restrict__ cent) {
    int row = blockIdx.x;
    int t   = threadIdx.x;  // 0..127, one float4 each
    float4 v = reinterpret_cast<const float4*>(cent + (size_t)row * ND)[t];
    float ss = v.x * v.x + v.y * v.y + v.z * v.z + v.w * v.w;
    #pragma unroll
    for (int o = 16; o > 0; o >>= 1) ss += __shfl_down_sync(0xffffffffu, ss, o);
    __shared__ float sred[4];
    if ((t & 31) == 0) sred[t >> 5] = ss;
    __syncthreads();
    float tot   = sred[0] + sred[1] + sred[2] + sred[3];
    float scale = 1.0f / fmaxf(sqrtf(tot), 1e-12f);
    float4 o4 = make_float4(v.x * scale, v.y * scale, v.z * scale, v.w * scale);
    reinterpret_cast<float4*>(g_cnorm + (size_t)row * ND)[t] = o4;
    __nv_bfloat162 p0 = __floats2bfloat162_rn(o4.x, o4.y);
    __nv_bfloat162 p1 = __floats2bfloat162_rn(o4.z, o4.w);
    uint2 pk = make_uint2(*reinterpret_cast<unsigned*>(&p0),
                          *reinterpret_cast<unsigned*>(&p1));
    reinterpret_cast<uint2*>(g_cnorm_bf)[ (size_t)row * (ND / 4) + t ] = pk;
}

// ---------------------------------------------------------------------------
// Kernel 2: bf16 tensor-core GEMM -> approx logits (fp32).
// Block tile 128x128, 8 warps (2M x 4N), warp tile 64x32, K chunks of 32.
// mma.sync.aligned.m16n8k16.row.col.f32.bf16.bf16.f32
// ---------------------------------------------------------------------------
#define SMSTRIDE 40  // 32 + 8 bf16 pad -> conflict-free fragment loads

__device__ __forceinline__ void mma16816(float* c, const unsigned* a, const unsigned* b) {
    asm volatile(
        "mma.sync.aligned.m16n8k16.row.col.f32.bf16.bf16.f32 "
        "{%0,%1,%2,%3},{%4,%5,%6,%7},{%8,%9},{%0,%1,%2,%3};\n"
        : "+f"(c[0]), "+f"(c[1]), "+f"(c[2]), "+f"(c[3])
        : "r"(a[0]), "r"(a[1]), "r"(a[2]), "r"(a[3]), "r"(b[0]), "r"(b[1]));
}

__global__ __launch_bounds__(256) void gemm_bf16(const float* __restrict__ q) {
    __shared__ __nv_bfloat16 sA[128 * SMSTRIDE];
    __shared__ __nv_bfloat16 sB[128 * SMSTRIDE];

    int tid   = threadIdx.x;
    int lane  = tid & 31, wid = tid >> 5;
    int warpM = wid & 1,  warpN = wid >> 1;     // 2 x 4 warp grid
    int g     = lane >> 2, tc = lane & 3;
    int m0 = blockIdx.y * 128, n0 = blockIdx.x * 128;

    float acc[4][4][4];
    #pragma unroll
    for (int mt = 0; mt < 4; mt++)
        #pragma unroll
        for (int nt = 0; nt < 4; nt++)
            #pragma unroll
            for (int i = 0; i < 4; i++) acc[mt][nt][i] = 0.0f;

    const float4* q4  = reinterpret_cast<const float4*>(q);
    const uint4*  c4p = reinterpret_cast<const uint4*>(g_cnorm_bf);

    for (int k0 = 0; k0 < ND; k0 += 32) {
        // Load A tile (128 rows x 32 k) fp32 -> bf16
        #pragma unroll
        for (int l = 0; l < 4; l++) {
            int e = tid + l * 256;          // 1024 float4s
            int row = e >> 3, c = e & 7;
            float4 v = q4[(size_t)(m0 + row) * (ND / 4) + (k0 >> 2) + c];
            __nv_bfloat162 p0 = __floats2bfloat162_rn(v.x, v.y);
            __nv_bfloat162 p1 = __floats2bfloat162_rn(v.z, v.w);
            uint2 pk = make_uint2(*reinterpret_cast<unsigned*>(&p0),
                                  *reinterpret_cast<unsigned*>(&p1));
            *reinterpret_cast<uint2*>(&sA[row * SMSTRIDE + c * 4]) = pk;
        }
        // Load B tile (128 centroid rows x 32 k) bf16
        #pragma unroll
        for (int l = 0; l < 2; l++) {
            int e = tid + l * 256;          // 512 uint4s
            int row = e >> 2, c = e & 3;
            uint4 v = c4p[(size_t)(n0 + row) * (ND / 8) + (k0 >> 3) + c];
            *reinterpret_cast<uint4*>(&sB[row * SMSTRIDE + c * 8]) = v;
        }
        __syncthreads();

        #pragma unroll
        for (int kk = 0; kk < 32; kk += 16) {
            unsigned a[4][4], b[4][2];
            #pragma unroll
            for (int mt = 0; mt < 4; mt++) {
                int rb = warpM * 64 + mt * 16;
                const __nv_bfloat16* base = &sA[(rb + g) * SMSTRIDE + kk + tc * 2];
                a[mt][0] = *reinterpret_cast<const unsigned*>(base);
                a[mt][1] = *reinterpret_cast<const unsigned*>(base + 8 * SMSTRIDE);
                a[mt][2] = *reinterpret_cast<const unsigned*>(base + 8);
                a[mt][3] = *reinterpret_cast<const unsigned*>(base + 8 * SMSTRIDE + 8);
            }
            #pragma unroll
            for (int nt = 0; nt < 4; nt++) {
                int cb = warpN * 32 + nt * 8;
                const __nv_bfloat16* base = &sB[(cb + g) * SMSTRIDE + kk + tc * 2];
                b[nt][0] = *reinterpret_cast<const unsigned*>(base);
                b[nt][1] = *reinterpret_cast<const unsigned*>(base + 8);
            }
            #pragma unroll
            for (int mt = 0; mt < 4; mt++)
                #pragma unroll
                for (int nt = 0; nt < 4; nt++)
                    mma16816(acc[mt][nt], a[mt], b[nt]);
        }
        __syncthreads();
    }

    // Store approx logits
    float2* out2 = reinterpret_cast<float2*>(g_logits);
    #pragma unroll
    for (int mt = 0; mt < 4; mt++) {
        #pragma unroll
        for (int nt = 0; nt < 4; nt++) {
            int r0  = m0 + warpM * 64 + mt * 16 + g;
            int col = n0 + warpN * 32 + nt * 8 + tc * 2;
            out2[((size_t)r0 * NP + col) >> 1] =
                make_float2(acc[mt][nt][0], acc[mt][nt][1]);
            out2[((size_t)(r0 + 8) * NP + col) >> 1] =
                make_float2(acc[mt][nt][2], acc[mt][nt][3]);
        }
    }
}

// ---------------------------------------------------------------------------
// Kernel 3: per-row argmax over approx logits + exact fp32 refinement of any
// candidates within MARGIN, then fused output writes.
// One warp per query row; 8 warps per block.
// ---------------------------------------------------------------------------
__global__ __launch_bounds__(256) void refine_and_write(
    const float* __restrict__ q, const float* __restrict__ cent,
    float* __restrict__ out) {
    const unsigned FULL = 0xffffffffu;
    int lane = threadIdx.x & 31;
    int w    = threadIdx.x >> 5;
    int b    = blockIdx.x * 8 + w;

    // Load this row's 1024 approx logits; lane l owns cols [l*32, l*32+32)
    const float4* l4 = reinterpret_cast<const float4*>(g_logits + (size_t)b * NP);
    float v[32];
    #pragma unroll
    for (int i = 0; i < 8; i++) {
        float4 t = l4[lane * 8 + i];
        v[i * 4 + 0] = t.x; v[i * 4 + 1] = t.y;
        v[i * 4 + 2] = t.z; v[i * 4 + 3] = t.w;
    }

    // Local argmax (ascending scan + strict '>' keeps first index)
    float bv = v[0]; int bi = 0;
    #pragma unroll
    for (int i = 1; i < 32; i++) if (v[i] > bv) { bv = v[i]; bi = i; }
    int bcol = lane * 32 + bi;

    // Warp argmax with first-index tie-break
    #pragma unroll
    for (int o = 16; o > 0; o >>= 1) {
        float ov = __shfl_down_sync(FULL, bv, o);
        int   oc = __shfl_down_sync(FULL, bcol, o);
        if (ov > bv || (ov == bv && oc < bcol)) { bv = ov; bcol = oc; }
    }
    bv   = __shfl_sync(FULL, bv, 0);
    bcol = __shfl_sync(FULL, bcol, 0);

    // Candidate mask within margin
    float thresh = bv - MARGIN;
    unsigned mask = 0;
    #pragma unroll
    for (int i = 0; i < 32; i++) mask |= (v[i] >= thresh) ? (1u << i) : 0u;
    int total = __reduce_add_sync(FULL, __popc(mask));

    int winner = bcol;
    if (total > 1) {
        const float4* qr = reinterpret_cast<const float4*>(q + (size_t)b * ND);
        float bestEx = -3.4e38f; int bestIdx = 0;
        for (;;) {
            unsigned act = __ballot_sync(FULL, mask != 0);
            if (!act) break;
            int L = __ffs(act) - 1;
            int bit = __ffs(mask) - 1;            // meaningful on lane L
            bit = __shfl_sync(FULL, bit, L);
            if (lane == L) mask &= mask - 1;
            int col = L * 32 + bit;               // processed in ascending order
            const float4* cr =
                reinterpret_cast<const float4*>(g_cnorm + (size_t)col * ND);
            float s = 0.0f;
            #pragma unroll
            for (int i = 0; i < 4; i++) {
                float4 a = qr[lane + 32 * i], c = cr[lane + 32 * i];
                s += a.x * c.x + a.y * c.y + a.z * c.z + a.w * c.w;
            }
            #pragma unroll
            for (int o = 16; o > 0; o >>= 1) s += __shfl_down_sync(FULL, s, o);
            s = __shfl_sync(FULL, s, 0);
            if (s > bestEx) { bestEx = s; bestIdx = col; }
        }
        winner = bestIdx;
    }

    // Outputs: context gather (raw centroids), hard index, one-hot 1.0
    const float4* wr = reinterpret_cast<const float4*>(cent + (size_t)winner * ND);
    float4* co = reinterpret_cast<float4*>(out + (size_t)b * ND);
    #pragma unroll
    for (int i = 0; i < 4; i++) co[lane + 32 * i] = wr[lane + 32 * i];
    if (lane == 0) {
        out[(size_t)NB * ND + b] = (float)winner;
        out[(size_t)NB * ND + NB + (size_t)b * NP + winner] = 1.0f;
    }
}

// ---------------------------------------------------------------------------
// Launch: out = [context (B*D) | hard (B) | routing (B*P)] as float32
// ---------------------------------------------------------------------------
extern "C" void kernel_launch(void* const* d_in, const int* in_sizes, int n_in,
                              void* d_out, int out_size) {
    const float* q    = (const float*)d_in[0];  // (B, D) fp32
    const float* cent = (const float*)d_in[1];  // (P, D) fp32
    float* out = (float*)d_out;

    normalize_centroids<<<NP, 128>>>(cent);
    gemm_bf16<<<dim3(8, 512), 256>>>(q);
    cudaMemsetAsync(out + (size_t)NB * ND + NB, 0,
                    (size_t)NB * NP * sizeof(float));
    refine_and_write<<<NB / 8, 256>>>(q, cent, out);
}

// round 3
// speedup vs baseline: 5.5749x; 1.0067x over previous
#include <cuda_runtime.h>
#include <cuda_bf16.h>

#define NB 65536   // batch
#define ND 512     // embed dim
#define NP 1024    // prototypes
#define MARGIN 0.08f
#define CAP 16

// Device-global scratch (no runtime allocation allowed)
static __device__ float          g_cnorm[NP * ND];      // normalized centroids fp32
static __device__ __nv_bfloat16  g_cnorm_bf[NP * ND];   // normalized centroids bf16

// Order-preserving float<->uint mapping (for atomicMax on floats)
__device__ __forceinline__ unsigned fmap(float f) {
    unsigned u = __float_as_uint(f);
    return (u & 0x80000000u) ? ~u : (u | 0x80000000u);
}
__device__ __forceinline__ float funmap(unsigned u) {
    u = (u & 0x80000000u) ? (u & 0x7fffffffu) : ~u;
    return __uint_as_float(u);
}

// ---------------------------------------------------------------------------
// Kernel 1: L2-normalize centroids -> fp32 + bf16 copies.
// ---------------------------------------------------------------------------
__global__ void normalize_centroids(const float* __restrict__ cent) {
    int row = blockIdx.x;
    int t   = threadIdx.x;  // 0..127, one float4 each
    float4 v = reinterpret_cast<const float4*>(cent + (size_t)row * ND)[t];
    float ss = v.x * v.x + v.y * v.y + v.z * v.z + v.w * v.w;
    #pragma unroll
    for (int o = 16; o > 0; o >>= 1) ss += __shfl_down_sync(0xffffffffu, ss, o);
    __shared__ float sred[4];
    if ((t & 31) == 0) sred[t >> 5] = ss;
    __syncthreads();
    float tot   = sred[0] + sred[1] + sred[2] + sred[3];
    float scale = 1.0f / fmaxf(sqrtf(tot), 1e-12f);
    float4 o4 = make_float4(v.x * scale, v.y * scale, v.z * scale, v.w * scale);
    reinterpret_cast<float4*>(g_cnorm + (size_t)row * ND)[t] = o4;
    __nv_bfloat162 p0 = __floats2bfloat162_rn(o4.x, o4.y);
    __nv_bfloat162 p1 = __floats2bfloat162_rn(o4.z, o4.w);
    uint2 pk = make_uint2(*reinterpret_cast<unsigned*>(&p0),
                          *reinterpret_cast<unsigned*>(&p1));
    reinterpret_cast<uint2*>(g_cnorm_bf)[(size_t)row * (ND / 4) + t] = pk;
}

// ---------------------------------------------------------------------------
// Kernel 2: fully fused. Block = 256 threads (8 warps), owns 128 query rows.
//  - q tile resident in smem as bf16 (128 x 512, padded stride 520)
//  - loop 8 N-chunks x 8 K-chunks; bf16 mma.sync; B double-buffered
//  - per-chunk running per-row max (smem atomicMax) + margin candidates
//  - exact fp32 refinement for multi-candidate rows
//  - fused writes: context gather, hard index, full one-hot row
// ---------------------------------------------------------------------------
#define ASTR 520      // 512 + 8 bf16 pad
#define BSTR 72       // 64 + 8 bf16 pad
#define SMEM_BYTES (128*ASTR*2 + 2*128*BSTR*2 + 128*4 + 128*4 + 128*CAP*2)

__device__ __forceinline__ void mma16816(float* c, const unsigned* a, const unsigned* b) {
    asm volatile(
        "mma.sync.aligned.m16n8k16.row.col.f32.bf16.bf16.f32 "
        "{%0,%1,%2,%3},{%4,%5,%6,%7},{%8,%9},{%0,%1,%2,%3};\n"
        : "+f"(c[0]), "+f"(c[1]), "+f"(c[2]), "+f"(c[3])
        : "r"(a[0]), "r"(a[1]), "r"(a[2]), "r"(a[3]), "r"(b[0]), "r"(b[1]));
}

__global__ __launch_bounds__(256, 1) void fused_kernel(
    const float* __restrict__ q, const float* __restrict__ cent,
    float* __restrict__ out) {
    extern __shared__ char sm_raw[];
    __nv_bfloat16* sA = reinterpret_cast<__nv_bfloat16*>(sm_raw);    // [128][ASTR]
    __nv_bfloat16* sB = sA + 128 * ASTR;                             // [2][128][BSTR]
    unsigned*       rowMaxU = reinterpret_cast<unsigned*>(sB + 2 * 128 * BSTR);
    int*            rowCnt  = reinterpret_cast<int*>(rowMaxU + 128);
    unsigned short* cand    = reinterpret_cast<unsigned short*>(rowCnt + 128);

    const unsigned FULL = 0xffffffffu;
    int tid  = threadIdx.x;
    int lane = tid & 31, wid = tid >> 5;
    int warpM = wid & 1, warpN = wid >> 1;   // 2 x 4 warp grid, warp tile 64x32
    int g = lane >> 2, tc = lane & 3;
    int m0 = blockIdx.x * 128;

    if (tid < 128) { rowMaxU[tid] = 0u; rowCnt[tid] = 0; }

    // ---- Load resident A tile: 128 x 512 fp32 -> bf16 ----
    const float4* q4 = reinterpret_cast<const float4*>(q);
    #pragma unroll 4
    for (int e = tid; e < 128 * 128; e += 256) {
        int row = e >> 7, c = e & 127;
        float4 v = q4[(size_t)(m0 + row) * 128 + c];
        __nv_bfloat162 p0 = __floats2bfloat162_rn(v.x, v.y);
        __nv_bfloat162 p1 = __floats2bfloat162_rn(v.z, v.w);
        uint2 pk = make_uint2(*reinterpret_cast<unsigned*>(&p0),
                              *reinterpret_cast<unsigned*>(&p1));
        *reinterpret_cast<uint2*>(&sA[row * ASTR + c * 4]) = pk;
    }

    float acc[4][4][4];
    #pragma unroll
    for (int mt = 0; mt < 4; mt++)
        #pragma unroll
        for (int nt = 0; nt < 4; nt++)
            #pragma unroll
            for (int i = 0; i < 4; i++) acc[mt][nt][i] = 0.0f;

    const uint4* cb4 = reinterpret_cast<const uint4*>(g_cnorm_bf);  // 8 bf16/uint4
    int lrow = tid >> 3, lcc = tid & 7;   // B loader: 4 uint4 per thread per chunk

    // Preload B chunk 0 (n0=0, k0=0)
    uint4 st[4];
    #pragma unroll
    for (int i = 0; i < 4; i++)
        st[i] = cb4[(size_t)(lrow + 32 * i) * 64 + lcc];
    #pragma unroll
    for (int i = 0; i < 4; i++)
        *reinterpret_cast<uint4*>(&sB[(lrow + 32 * i) * BSTR + lcc * 8]) = st[i];

    // ---- Main loop: 64 chunks = 8 n-tiles x 8 k-steps of 64 ----
    for (int c = 0; c < 64; c++) {
        __syncthreads();
        if (c + 1 < 64) {
            int n0n = ((c + 1) >> 3) * 128, k0n = ((c + 1) & 7) * 64;
            #pragma unroll
            for (int i = 0; i < 4; i++)
                st[i] = cb4[(size_t)(n0n + lrow + 32 * i) * 64 + (k0n >> 3) + lcc];
        }
        const __nv_bfloat16* B = sB + (c & 1) * 128 * BSTR;
        int kbase = (c & 7) * 64;

        #pragma unroll
        for (int kk = 0; kk < 64; kk += 16) {
            unsigned a[4][4], b[4][2];
            #pragma unroll
            for (int mt = 0; mt < 4; mt++) {
                const __nv_bfloat16* base =
                    &sA[(warpM * 64 + mt * 16 + g) * ASTR + kbase + kk + tc * 2];
                a[mt][0] = *reinterpret_cast<const unsigned*>(base);
                a[mt][1] = *reinterpret_cast<const unsigned*>(base + 8 * ASTR);
                a[mt][2] = *reinterpret_cast<const unsigned*>(base + 8);
                a[mt][3] = *reinterpret_cast<const unsigned*>(base + 8 * ASTR + 8);
            }
            #pragma unroll
            for (int nt = 0; nt < 4; nt++) {
                const __nv_bfloat16* base =
                    &B[(warpN * 32 + nt * 8 + g) * BSTR + kk + tc * 2];
                b[nt][0] = *reinterpret_cast<const unsigned*>(base);
                b[nt][1] = *reinterpret_cast<const unsigned*>(base + 8);
            }
            #pragma unroll
            for (int mt = 0; mt < 4; mt++)
                #pragma unroll
                for (int nt = 0; nt < 4; nt++)
                    mma16816(acc[mt][nt], a[mt], b[nt]);
        }

        if (c + 1 < 64) {
            __nv_bfloat16* Bn = sB + ((c + 1) & 1) * 128 * BSTR;
            #pragma unroll
            for (int i = 0; i < 4; i++)
                *reinterpret_cast<uint4*>(&Bn[(lrow + 32 * i) * BSTR + lcc * 8]) = st[i];
        }

        if ((c & 7) == 7) {   // n-tile finished: argmax epilogue
            int n0 = (c >> 3) * 128;
            #pragma unroll
            for (int mt = 0; mt < 4; mt++) {
                float v0 = -3.4e38f, v1 = -3.4e38f;
                #pragma unroll
                for (int nt = 0; nt < 4; nt++) {
                    v0 = fmaxf(v0, fmaxf(acc[mt][nt][0], acc[mt][nt][1]));
                    v1 = fmaxf(v1, fmaxf(acc[mt][nt][2], acc[mt][nt][3]));
                }
                v0 = fmaxf(v0, __shfl_xor_sync(FULL, v0, 1));
                v0 = fmaxf(v0, __shfl_xor_sync(FULL, v0, 2));
                v1 = fmaxf(v1, __shfl_xor_sync(FULL, v1, 1));
                v1 = fmaxf(v1, __shfl_xor_sync(FULL, v1, 2));
                if (tc == 0) {
                    int r = warpM * 64 + mt * 16 + g;
                    atomicMax(&rowMaxU[r], fmap(v0));
                    atomicMax(&rowMaxU[r + 8], fmap(v1));
                }
            }
            __syncthreads();
            #pragma unroll
            for (int mt = 0; mt < 4; mt++) {
                int r0 = warpM * 64 + mt * 16 + g;
                float th0 = funmap(rowMaxU[r0]) - MARGIN;
                float th1 = funmap(rowMaxU[r0 + 8]) - MARGIN;
                #pragma unroll
                for (int nt = 0; nt < 4; nt++) {
                    #pragma unroll
                    for (int i = 0; i < 4; i++) {
                        float v = acc[mt][nt][i];
                        int   r = (i < 2) ? r0 : r0 + 8;
                        float th = (i < 2) ? th0 : th1;
                        if (v >= th) {
                            int p = atomicAdd(&rowCnt[r], 1);
                            if (p < CAP)
                                cand[r * CAP + p] = (unsigned short)
                                    (n0 + warpN * 32 + nt * 8 + tc * 2 + (i & 1));
                        }
                        acc[mt][nt][i] = 0.0f;
                    }
                }
            }
        }
    }
    __syncthreads();

    // ---- Refinement + output writes: warp w owns rows [w*16, w*16+16) ----
    const float4* c4n = reinterpret_cast<const float4*>(g_cnorm);
    const float4* ce4 = reinterpret_cast<const float4*>(cent);
    float* outHard = out + (size_t)NB * ND;
    float* outOH   = outHard + NB;

    for (int rr = 0; rr < 16; rr++) {
        int r = wid * 16 + rr;
        int b = m0 + r;
        int cnt = rowCnt[r];
        int winner;
        if (cnt == 1) {
            winner = cand[r * CAP];
        } else {
            // exact fp32 dots; q row cached in registers
            float4 aq[4];
            const float4* qr = q4 + (size_t)b * 128;
            #pragma unroll
            for (int i = 0; i < 4; i++) aq[i] = qr[lane + 32 * i];
            float bv = -3.4e38f; int bi = NP;
            int lim = (cnt <= CAP) ? cnt : NP;   // overflow -> full exact scan
            for (int j = 0; j < lim; j++) {
                int col = (cnt <= CAP) ? (int)cand[r * CAP + j] : j;
                const float4* cr = c4n + (size_t)col * 128;
                float s = 0.0f;
                #pragma unroll
                for (int i = 0; i < 4; i++) {
                    float4 cc = cr[lane + 32 * i];
                    s = fmaf(aq[i].x, cc.x, fmaf(aq[i].y, cc.y,
                        fmaf(aq[i].z, cc.z, fmaf(aq[i].w, cc.w, s))));
                }
                #pragma unroll
                for (int o = 16; o > 0; o >>= 1)
                    s += __shfl_xor_sync(FULL, s, o);
                if (s > bv || (s == bv && col < bi)) { bv = s; bi = col; }
            }
            winner = bi;
        }

        // context gather (raw centroids)
        float4* ctx = reinterpret_cast<float4*>(out + (size_t)b * ND);
        #pragma unroll
        for (int i = 0; i < 4; i++)
            ctx[lane + 32 * i] = ce4[(size_t)winner * 128 + lane + 32 * i];
        if (lane == 0) outHard[b] = (float)winner;
        // full one-hot row (zeros + 1.0)
        float4* oh = reinterpret_cast<float4*>(outOH + (size_t)b * NP);
        int wq = winner >> 2, wr = winner & 3;
        #pragma unroll
        for (int i = 0; i < 8; i++) {
            int j = lane + 32 * i;
            float4 z = make_float4(0.f, 0.f, 0.f, 0.f);
            if (j == wq) reinterpret_cast<float*>(&z)[wr] = 1.0f;
            oh[j] = z;
        }
    }
}

// ---------------------------------------------------------------------------
// Launch: out = [context (B*D) | hard (B) | routing (B*P)] as float32
// ---------------------------------------------------------------------------
extern "C" void kernel_launch(void* const* d_in, const int* in_sizes, int n_in,
                              void* d_out, int out_size) {
    const float* q    = (const float*)d_in[0];  // (B, D) fp32
    const float* cent = (const float*)d_in[1];  // (P, D) fp32
    float* out = (float*)d_out;

    cudaFuncSetAttribute(fused_kernel,
                         cudaFuncAttributeMaxDynamicSharedMemorySize, SMEM_BYTES);
    normalize_centroids<<<NP, 128>>>(cent);
    fused_kernel<<<NB / 128, 256, SMEM_BYTES>>>(q, cent, out);
}